// round 13
// baseline (speedup 1.0000x reference)
#include <cuda_runtime.h>
#include <cuda_fp16.h>

// GraphSAGE 3-layer GCN aggregator. N=100000, E=1600000, 64->64->64->40.
//
// Restructure: ((segsum(h[src]) + h) * inv) @ W^T + b
//            = (segsum(p[src])  + p) * inv + b   with p = h @ W^T
// p stored in fp16 (one 128B line per node row); accum/weights fp32.
// Gather: ONE WARP PER NODE = 4 edge-slots x 8 column-chunks (16B/lane).
// Projection: gemm-style, W column held in per-thread REGISTERS; smem reads
// of h are warp-uniform float4 broadcasts (1 crossbar phase, not 4).

constexpr int NN = 100000;
constexpr int NE = 1600000;
constexpr int NB = (NN + 1023) / 1024;  // 98 scan blocks

__device__ __half g_pA[NN * 64];
__device__ __half g_pB[NN * 64];
__device__ int    g_deg[NN];
__device__ int    g_off[NN + 1];
__device__ int    g_cur[NN];
__device__ int    g_esrc[NE];
__device__ int    g_bsum[NB];

// ---------------------------------------------------------------- degrees ---
__global__ void deg_zero_k() {
    int i = blockIdx.x * 256 + threadIdx.x;
    if (i < NN) g_deg[i] = 0;
}

__global__ void deg_count_k(const int4* __restrict__ dst4) {
    int i = blockIdx.x * 256 + threadIdx.x;
    if (i < NE / 4) {
        int4 d = __ldg(&dst4[i]);
        atomicAdd(&g_deg[d.x], 1);
        atomicAdd(&g_deg[d.y], 1);
        atomicAdd(&g_deg[d.z], 1);
        atomicAdd(&g_deg[d.w], 1);
    }
}

// ------------------------------------------------------------------- scan ---
__global__ __launch_bounds__(1024) void scan_bsum_k() {
    int i = blockIdx.x * 1024 + threadIdx.x;
    int v = (i < NN) ? g_deg[i] : 0;
#pragma unroll
    for (int o = 16; o; o >>= 1) v += __shfl_down_sync(~0u, v, o);
    __shared__ int ws[32];
    if ((threadIdx.x & 31) == 0) ws[threadIdx.x >> 5] = v;
    __syncthreads();
    if (threadIdx.x < 32) {
        int s = ws[threadIdx.x];
#pragma unroll
        for (int o = 16; o; o >>= 1) s += __shfl_down_sync(~0u, s, o);
        if (threadIdx.x == 0) g_bsum[blockIdx.x] = s;
    }
}

// scan_write with inlined cross-block partials (each block sums g_bsum[<bid]).
__global__ __launch_bounds__(1024) void scan_write_k() {
    const int lane = threadIdx.x & 31, w = threadIdx.x >> 5;

    int part = (threadIdx.x < blockIdx.x) ? g_bsum[threadIdx.x] : 0;
#pragma unroll
    for (int o = 16; o; o >>= 1) part += __shfl_down_sync(~0u, part, o);
    __shared__ int ws2[32];
    if (lane == 0) ws2[w] = part;
    __syncthreads();
    __shared__ int boff_s;
    if (threadIdx.x < 32) {
        int s = ws2[threadIdx.x];
#pragma unroll
        for (int o = 16; o; o >>= 1) s += __shfl_down_sync(~0u, s, o);
        if (threadIdx.x == 0) boff_s = s;
    }

    int i = blockIdx.x * 1024 + threadIdx.x;
    int v = (i < NN) ? g_deg[i] : 0;
    int x = v;
#pragma unroll
    for (int o = 1; o < 32; o <<= 1) {
        int y = __shfl_up_sync(~0u, x, o);
        if (lane >= o) x += y;
    }
    __shared__ int ws[32], sws[32];
    if (lane == 31) ws[w] = x;
    __syncthreads();
    if (threadIdx.x < 32) {
        int s = ws[threadIdx.x];
        int xx = s;
#pragma unroll
        for (int o = 1; o < 32; o <<= 1) {
            int y = __shfl_up_sync(~0u, xx, o);
            if (lane >= o) xx += y;
        }
        sws[threadIdx.x] = xx - s;  // exclusive warp prefix
    }
    __syncthreads();
    int incl = x + sws[w] + boff_s;
    int excl = incl - v;
    if (i < NN) {
        g_off[i] = excl;
        g_cur[i] = excl;
        if (i == NN - 1) g_off[NN] = incl;
    }
}

// ------------------------------------------------------------------- fill ---
__global__ void fill_k(const int4* __restrict__ src4,
                       const int4* __restrict__ dst4) {
    int i = blockIdx.x * 256 + threadIdx.x;
    if (i < NE / 4) {
        int4 s = __ldg(&src4[i]);
        int4 d = __ldg(&dst4[i]);
        g_esrc[atomicAdd(&g_cur[d.x], 1)] = s.x;
        g_esrc[atomicAdd(&g_cur[d.y], 1)] = s.y;
        g_esrc[atomicAdd(&g_cur[d.z], 1)] = s.z;
        g_esrc[atomicAdd(&g_cur[d.w], 1)] = s.w;
    }
}

// --------------------------------------------------------------- gather -----
__device__ __forceinline__ void add8(float acc[8], uint4 u) {
    __half2* h = reinterpret_cast<__half2*>(&u);
#pragma unroll
    for (int j = 0; j < 4; j++) {
        float2 f = __half22float2(h[j]);
        acc[2 * j]     += f.x;
        acc[2 * j + 1] += f.y;
    }
}

// Warp-collective gather of one node's aggregated row (self + neighbors).
__device__ __forceinline__ void gather_node(const __half* __restrict__ pin,
                                            int node, int s0, int s1,
                                            int es, int c, float acc[8]) {
#pragma unroll
    for (int j = 0; j < 8; j++) acc[j] = 0.f;
    if (es == 0)
        add8(acc, __ldg(reinterpret_cast<const uint4*>(pin + node * 64) + c));

    int e = s0;
    for (; e + 8 <= s1; e += 8) {
        int i0 = __ldg(&g_esrc[e + es]);
        int i1 = __ldg(&g_esrc[e + 4 + es]);
        uint4 u0 = __ldg(reinterpret_cast<const uint4*>(pin + i0 * 64) + c);
        uint4 u1 = __ldg(reinterpret_cast<const uint4*>(pin + i1 * 64) + c);
        add8(acc, u0);
        add8(acc, u1);
    }
    for (; e < s1; e += 4) {
        int ee = e + es;
        if (ee < s1) {
            int i0 = __ldg(&g_esrc[ee]);
            add8(acc, __ldg(reinterpret_cast<const uint4*>(pin + i0 * 64) + c));
        }
    }
#pragma unroll
    for (int j = 0; j < 8; j++) {
        acc[j] += __shfl_xor_sync(~0u, acc[j], 8);
        acc[j] += __shfl_xor_sync(~0u, acc[j], 16);
    }
}

// ------------------------------------------------------------------- gemm ---
// k0: p0 = feats @ W0^T (fp32 in, fp16 out). Block (64,8)=512thr, 64 nodes.
// hs rows read as warp-uniform float4 broadcasts.
__global__ __launch_bounds__(512) void gemm_k(const float* __restrict__ h,
                                              const float* __restrict__ W,
                                              __half* __restrict__ p) {
    __shared__ float Ws[64 * 65];
    __shared__ __align__(16) float hs[8][64];
    const int tx = threadIdx.x, ty = threadIdx.y;
    const int tid = ty * 64 + tx;
    for (int i = tid; i < 64 * 64; i += 512)
        Ws[(i >> 6) * 65 + (i & 63)] = W[i];
    __syncthreads();
    float w[64];
#pragma unroll
    for (int k = 0; k < 64; k++) w[k] = Ws[tx * 65 + k];

    const int base = blockIdx.x * 64;
#pragma unroll
    for (int it = 0; it < 8; it++) {
        int n = base + it * 8 + ty;
        __syncthreads();
        if (n < NN) hs[ty][tx] = h[n * 64 + tx];
        __syncthreads();
        if (n < NN) {
            const float4* hrow = reinterpret_cast<const float4*>(&hs[ty][0]);
            float acc = 0.f;
#pragma unroll
            for (int k4 = 0; k4 < 16; k4++) {
                float4 hv = hrow[k4];
                acc = fmaf(hv.x, w[4 * k4 + 0], acc);
                acc = fmaf(hv.y, w[4 * k4 + 1], acc);
                acc = fmaf(hv.z, w[4 * k4 + 2], acc);
                acc = fmaf(hv.w, w[4 * k4 + 3], acc);
            }
            p[n * 64 + tx] = __float2half_rn(acc);
        }
    }
}

// ---------------------------------------------------------- fused layer -----
// 256 threads = 8 warps = 8 nodes/block (grid 12500 exact).
// Phase 1: each warp gathers one node; epilogue relu(agg*inv + b) -> hs.
// Phase 2: projection, gemm-style: thread owns output column o=tid&63 with
// W column in registers; 4 groups x 2 nodes each; h via float4 broadcasts.
// pout is fp16, stride 64, zero-filled for o >= DO.
template <int DO>
__global__ __launch_bounds__(256, 2) void layer_k(const float* __restrict__ bv,
                                                  const float* __restrict__ W,
                                                  const __half* __restrict__ pin,
                                                  __half* __restrict__ pout) {
    __shared__ float Ws[64 * 65];
    __shared__ __align__(16) float hs[8][68];
    const int tid = threadIdx.x;
    const int warp = tid >> 5, lane = tid & 31;
    const int es = lane >> 3, c = lane & 7;
    const int node = blockIdx.x * 8 + warp;

    for (int i = tid; i < DO * 64; i += 256)
        Ws[(i >> 6) * 65 + (i & 63)] = W[i];

    const int s0 = __ldg(&g_off[node]);
    const int s1 = __ldg(&g_off[node + 1]);

    float acc[8];
    gather_node(pin, node, s0, s1, es, c, acc);

    if (es == 0) {
        float inv = 1.f / (float)(s1 - s0 + 1);
        const float4* bv4 = reinterpret_cast<const float4*>(bv);
        float4 b0 = __ldg(&bv4[c * 2]);
        float4 b1 = __ldg(&bv4[c * 2 + 1]);
        float4 r0, r1;
        r0.x = fmaxf(fmaf(acc[0], inv, b0.x), 0.f);
        r0.y = fmaxf(fmaf(acc[1], inv, b0.y), 0.f);
        r0.z = fmaxf(fmaf(acc[2], inv, b0.z), 0.f);
        r0.w = fmaxf(fmaf(acc[3], inv, b0.w), 0.f);
        r1.x = fmaxf(fmaf(acc[4], inv, b1.x), 0.f);
        r1.y = fmaxf(fmaf(acc[5], inv, b1.y), 0.f);
        r1.z = fmaxf(fmaf(acc[6], inv, b1.z), 0.f);
        r1.w = fmaxf(fmaf(acc[7], inv, b1.w), 0.f);
        float4* hrow = reinterpret_cast<float4*>(&hs[warp][0]);
        hrow[c * 2]     = r0;
        hrow[c * 2 + 1] = r1;
    }
    __syncthreads();

    // projection: 4 groups of 64 threads; group handles 2 nodes.
    const int o = tid & 63;
    const int grp = tid >> 6;  // 0..3
    float w[64];
    if (DO == 64 || o < DO) {
#pragma unroll
        for (int k = 0; k < 64; k++) w[k] = Ws[o * 65 + k];  // conflict-free
    }
#pragma unroll
    for (int t = 0; t < 2; t++) {
        int n = grp * 2 + t;
        float a = 0.f;
        if (DO == 64 || o < DO) {
            const float4* hrow = reinterpret_cast<const float4*>(&hs[n][0]);
#pragma unroll
            for (int k4 = 0; k4 < 16; k4++) {
                float4 hv = hrow[k4];  // warp-uniform broadcast
                a = fmaf(hv.x, w[4 * k4 + 0], a);
                a = fmaf(hv.y, w[4 * k4 + 1], a);
                a = fmaf(hv.z, w[4 * k4 + 2], a);
                a = fmaf(hv.w, w[4 * k4 + 3], a);
            }
        }
        pout[(blockIdx.x * 8 + n) * 64 + o] = __float2half_rn(a);
    }
}

// ------------------------------------------------------------- final layer --
// out = (gather p2 + self)*inv + b2, 40 cols (chunks 5..7 of p2 are zeros).
__global__ __launch_bounds__(256) void fin_k(const float* __restrict__ bv,
                                             const __half* __restrict__ pin,
                                             float* __restrict__ out) {
    const int tid = threadIdx.x;
    const int warp = tid >> 5, lane = tid & 31;
    const int es = lane >> 3, c = lane & 7;
    const int node = blockIdx.x * 8 + warp;

    const int s0 = __ldg(&g_off[node]);
    const int s1 = __ldg(&g_off[node + 1]);

    float acc[8];
    gather_node(pin, node, s0, s1, es, c, acc);

    if (es == 0 && c < 5) {
        float inv = 1.f / (float)(s1 - s0 + 1);
        const float4* bv4 = reinterpret_cast<const float4*>(bv);
        float4 b0 = __ldg(&bv4[c * 2]);
        float4 b1 = __ldg(&bv4[c * 2 + 1]);
        float4 r0, r1;
        r0.x = fmaf(acc[0], inv, b0.x);
        r0.y = fmaf(acc[1], inv, b0.y);
        r0.z = fmaf(acc[2], inv, b0.z);
        r0.w = fmaf(acc[3], inv, b0.w);
        r1.x = fmaf(acc[4], inv, b1.x);
        r1.y = fmaf(acc[5], inv, b1.y);
        r1.z = fmaf(acc[6], inv, b1.z);
        r1.w = fmaf(acc[7], inv, b1.w);
        float4* out4 = reinterpret_cast<float4*>(out);
        out4[node * 10 + c * 2]     = r0;
        out4[node * 10 + c * 2 + 1] = r1;
    }
}

// ----------------------------------------------------------------- launch ---
extern "C" void kernel_launch(void* const* d_in, const int* in_sizes, int n_in,
                              void* d_out, int out_size) {
    const float* feats = (const float*)d_in[0];
    const int*   src   = (const int*)d_in[1];
    const int*   dst   = (const int*)d_in[2];
    const float* W0 = (const float*)d_in[3];
    const float* b0 = (const float*)d_in[4];
    const float* W1 = (const float*)d_in[5];
    const float* b1 = (const float*)d_in[6];
    const float* W2 = (const float*)d_in[7];
    const float* b2 = (const float*)d_in[8];
    float* out = (float*)d_out;

    void *pA_v = nullptr, *pB_v = nullptr;
    cudaGetSymbolAddress(&pA_v, g_pA);
    cudaGetSymbolAddress(&pB_v, g_pB);
    __half* pA = (__half*)pA_v;
    __half* pB = (__half*)pB_v;

    // CSR build
    deg_zero_k<<<(NN + 255) / 256, 256>>>();
    deg_count_k<<<(NE / 4 + 255) / 256, 256>>>((const int4*)dst);
    scan_bsum_k<<<NB, 1024>>>();
    scan_write_k<<<NB, 1024>>>();
    fill_k<<<(NE / 4 + 255) / 256, 256>>>((const int4*)src, (const int4*)dst);

    // k0: p0 = feats @ W0^T
    gemm_k<<<(NN + 63) / 64, dim3(64, 8)>>>(feats, W0, pA);
    // k1: h1 = relu(agg(p0)*inv + b0); p1 = h1 @ W1^T
    layer_k<64><<<NN / 8, 256>>>(b0, W1, pA, pB);
    // k2: h2 = relu(agg(p1)*inv + b1); p2 = h2 @ W2^T (40-wide, zero-padded)
    layer_k<40><<<NN / 8, 256>>>(b1, W2, pB, pA);
    // k3: out = agg(p2)*inv + b2
    fin_k<<<NN / 8, 256>>>(b2, pA, out);
}

// round 14
// speedup vs baseline: 1.0898x; 1.0898x over previous
#include <cuda_runtime.h>
#include <cuda_fp16.h>

// GraphSAGE 3-layer GCN aggregator. N=100000, E=1600000, 64->64->64->40.
//
// Restructure: ((segsum(h[src]) + h) * inv) @ W^T + b
//            = (segsum(p[src])  + p) * inv + b   with p = h @ W^T
// p stored fp16 (one 128B line per node row); accum/weights fp32.
// layer_k: 512 threads, 64 nodes/block.
//   Phase A: 16 warps x 4 nodes warp-collective gather (16 edges in flight),
//            epilogue relu(agg*inv+b) -> hs[64][68] (fp32).
//   Phase B: thread tx owns W column in 64 REGISTERS (filled once per block,
//            conflict-free stride-65 smem), 8 nodes per thread, h read as
//            warp-uniform float4 broadcasts (1 crossbar phase).

constexpr int NN = 100000;
constexpr int NE = 1600000;
constexpr int NB = (NN + 1023) / 1024;  // 98 scan blocks

__device__ __half g_pA[NN * 64];
__device__ __half g_pB[NN * 64];
__device__ int    g_deg[NN];
__device__ int    g_off[NN + 1];
__device__ int    g_cur[NN];
__device__ int    g_esrc[NE];
__device__ int    g_bsum[NB];

// ---------------------------------------------------------------- degrees ---
__global__ void deg_zero_k() {
    int i = blockIdx.x * 256 + threadIdx.x;
    if (i < NN) g_deg[i] = 0;
}

__global__ void deg_count_k(const int4* __restrict__ dst4) {
    int i = blockIdx.x * 256 + threadIdx.x;
    if (i < NE / 4) {
        int4 d = __ldg(&dst4[i]);
        atomicAdd(&g_deg[d.x], 1);
        atomicAdd(&g_deg[d.y], 1);
        atomicAdd(&g_deg[d.z], 1);
        atomicAdd(&g_deg[d.w], 1);
    }
}

// ------------------------------------------------------------------- scan ---
__global__ __launch_bounds__(1024) void scan_bsum_k() {
    int i = blockIdx.x * 1024 + threadIdx.x;
    int v = (i < NN) ? g_deg[i] : 0;
#pragma unroll
    for (int o = 16; o; o >>= 1) v += __shfl_down_sync(~0u, v, o);
    __shared__ int ws[32];
    if ((threadIdx.x & 31) == 0) ws[threadIdx.x >> 5] = v;
    __syncthreads();
    if (threadIdx.x < 32) {
        int s = ws[threadIdx.x];
#pragma unroll
        for (int o = 16; o; o >>= 1) s += __shfl_down_sync(~0u, s, o);
        if (threadIdx.x == 0) g_bsum[blockIdx.x] = s;
    }
}

// scan_write with inlined cross-block partials (each block sums g_bsum[<bid]).
__global__ __launch_bounds__(1024) void scan_write_k() {
    const int lane = threadIdx.x & 31, w = threadIdx.x >> 5;

    int part = (threadIdx.x < blockIdx.x) ? g_bsum[threadIdx.x] : 0;
#pragma unroll
    for (int o = 16; o; o >>= 1) part += __shfl_down_sync(~0u, part, o);
    __shared__ int ws2[32];
    if (lane == 0) ws2[w] = part;
    __syncthreads();
    __shared__ int boff_s;
    if (threadIdx.x < 32) {
        int s = ws2[threadIdx.x];
#pragma unroll
        for (int o = 16; o; o >>= 1) s += __shfl_down_sync(~0u, s, o);
        if (threadIdx.x == 0) boff_s = s;
    }

    int i = blockIdx.x * 1024 + threadIdx.x;
    int v = (i < NN) ? g_deg[i] : 0;
    int x = v;
#pragma unroll
    for (int o = 1; o < 32; o <<= 1) {
        int y = __shfl_up_sync(~0u, x, o);
        if (lane >= o) x += y;
    }
    __shared__ int ws[32], sws[32];
    if (lane == 31) ws[w] = x;
    __syncthreads();
    if (threadIdx.x < 32) {
        int s = ws[threadIdx.x];
        int xx = s;
#pragma unroll
        for (int o = 1; o < 32; o <<= 1) {
            int y = __shfl_up_sync(~0u, xx, o);
            if (lane >= o) xx += y;
        }
        sws[threadIdx.x] = xx - s;  // exclusive warp prefix
    }
    __syncthreads();
    int incl = x + sws[w] + boff_s;
    int excl = incl - v;
    if (i < NN) {
        g_off[i] = excl;
        g_cur[i] = excl;
        if (i == NN - 1) g_off[NN] = incl;
    }
}

// ------------------------------------------------------------------- fill ---
__global__ void fill_k(const int4* __restrict__ src4,
                       const int4* __restrict__ dst4) {
    int i = blockIdx.x * 256 + threadIdx.x;
    if (i < NE / 4) {
        int4 s = __ldg(&src4[i]);
        int4 d = __ldg(&dst4[i]);
        g_esrc[atomicAdd(&g_cur[d.x], 1)] = s.x;
        g_esrc[atomicAdd(&g_cur[d.y], 1)] = s.y;
        g_esrc[atomicAdd(&g_cur[d.z], 1)] = s.z;
        g_esrc[atomicAdd(&g_cur[d.w], 1)] = s.w;
    }
}

// --------------------------------------------------------------- gather -----
__device__ __forceinline__ void add8(float acc[8], uint4 u) {
    __half2* h = reinterpret_cast<__half2*>(&u);
#pragma unroll
    for (int j = 0; j < 4; j++) {
        float2 f = __half22float2(h[j]);
        acc[2 * j]     += f.x;
        acc[2 * j + 1] += f.y;
    }
}

// Warp-collective gather of one node's aggregated row (self + neighbors).
// es = lane>>3 (edge slot 0..3), c = lane&7 (16B column chunk).
__device__ __forceinline__ void gather_node(const __half* __restrict__ pin,
                                            int node, int s0, int s1,
                                            int es, int c, float acc[8]) {
#pragma unroll
    for (int j = 0; j < 8; j++) acc[j] = 0.f;
    if (es == 0)
        add8(acc, __ldg(reinterpret_cast<const uint4*>(pin + node * 64) + c));

    int e = s0;
    for (; e + 16 <= s1; e += 16) {  // 4 idx + 4 rows in flight per lane
        int i0 = __ldg(&g_esrc[e + es]);
        int i1 = __ldg(&g_esrc[e + 4 + es]);
        int i2 = __ldg(&g_esrc[e + 8 + es]);
        int i3 = __ldg(&g_esrc[e + 12 + es]);
        uint4 u0 = __ldg(reinterpret_cast<const uint4*>(pin + i0 * 64) + c);
        uint4 u1 = __ldg(reinterpret_cast<const uint4*>(pin + i1 * 64) + c);
        uint4 u2 = __ldg(reinterpret_cast<const uint4*>(pin + i2 * 64) + c);
        uint4 u3 = __ldg(reinterpret_cast<const uint4*>(pin + i3 * 64) + c);
        add8(acc, u0);
        add8(acc, u1);
        add8(acc, u2);
        add8(acc, u3);
    }
    for (; e + 8 <= s1; e += 8) {
        int i0 = __ldg(&g_esrc[e + es]);
        int i1 = __ldg(&g_esrc[e + 4 + es]);
        uint4 u0 = __ldg(reinterpret_cast<const uint4*>(pin + i0 * 64) + c);
        uint4 u1 = __ldg(reinterpret_cast<const uint4*>(pin + i1 * 64) + c);
        add8(acc, u0);
        add8(acc, u1);
    }
    for (; e < s1; e += 4) {
        int ee = e + es;
        if (ee < s1) {
            int i0 = __ldg(&g_esrc[ee]);
            add8(acc, __ldg(reinterpret_cast<const uint4*>(pin + i0 * 64) + c));
        }
    }
#pragma unroll
    for (int j = 0; j < 8; j++) {
        acc[j] += __shfl_xor_sync(~0u, acc[j], 8);
        acc[j] += __shfl_xor_sync(~0u, acc[j], 16);
    }
}

// ------------------------------------------------------------------- gemm ---
// k0: p0 = feats @ W0^T (fp32 in, fp16 out). Block (64,8)=512thr, 64 nodes.
__global__ __launch_bounds__(512) void gemm_k(const float* __restrict__ h,
                                              const float* __restrict__ W,
                                              __half* __restrict__ p) {
    __shared__ float Ws[64 * 65];
    __shared__ __align__(16) float hs[8][64];
    const int tx = threadIdx.x, ty = threadIdx.y;
    const int tid = ty * 64 + tx;
    for (int i = tid; i < 64 * 64; i += 512)
        Ws[(i >> 6) * 65 + (i & 63)] = W[i];
    __syncthreads();
    float w[64];
#pragma unroll
    for (int k = 0; k < 64; k++) w[k] = Ws[tx * 65 + k];

    const int base = blockIdx.x * 64;
#pragma unroll
    for (int it = 0; it < 8; it++) {
        int n = base + it * 8 + ty;
        __syncthreads();
        if (n < NN) hs[ty][tx] = h[n * 64 + tx];
        __syncthreads();
        if (n < NN) {
            const float4* hrow = reinterpret_cast<const float4*>(&hs[ty][0]);
            float acc = 0.f;
#pragma unroll
            for (int k4 = 0; k4 < 16; k4++) {
                float4 hv = hrow[k4];
                acc = fmaf(hv.x, w[4 * k4 + 0], acc);
                acc = fmaf(hv.y, w[4 * k4 + 1], acc);
                acc = fmaf(hv.z, w[4 * k4 + 2], acc);
                acc = fmaf(hv.w, w[4 * k4 + 3], acc);
            }
            p[n * 64 + tx] = __float2half_rn(acc);
        }
    }
}

// ---------------------------------------------------------- fused layer -----
// 512 threads (16 warps), 64 nodes per block. Grid 1563 (last block partial).
// Phase A: warp gathers 4 nodes; epilogue relu(agg*inv + b) -> hs rows.
// Phase B: thread tx owns output col with W column in regs; ty handles 8
// nodes; h via warp-uniform float4 broadcasts. pout fp16 stride 64,
// zero-filled for o >= DO.
template <int DO>
__global__ __launch_bounds__(512) void layer_k(const float* __restrict__ bv,
                                               const float* __restrict__ W,
                                               const __half* __restrict__ pin,
                                               __half* __restrict__ pout) {
    __shared__ float Ws[64 * 65];
    __shared__ __align__(16) float hs[64][68];
    const int tid = threadIdx.y * 64 + threadIdx.x;
    const int warp = tid >> 5, lane = tid & 31;
    const int es = lane >> 3, c = lane & 7;
    const int nbase = blockIdx.x * 64;

    for (int i = tid; i < DO * 64; i += 512)
        Ws[(i >> 6) * 65 + (i & 63)] = W[i];

    // Phase A: gather 4 nodes per warp
#pragma unroll 1
    for (int i = 0; i < 4; i++) {
        const int nl = warp * 4 + i;
        const int node = nbase + nl;
        if (node < NN) {
            const int s0 = __ldg(&g_off[node]);
            const int s1 = __ldg(&g_off[node + 1]);
            float acc[8];
            gather_node(pin, node, s0, s1, es, c, acc);
            if (es == 0) {
                float inv = 1.f / (float)(s1 - s0 + 1);
                const float4* bv4 = reinterpret_cast<const float4*>(bv);
                float4 b0 = __ldg(&bv4[c * 2]);
                float4 b1 = __ldg(&bv4[c * 2 + 1]);
                float4 r0, r1;
                r0.x = fmaxf(fmaf(acc[0], inv, b0.x), 0.f);
                r0.y = fmaxf(fmaf(acc[1], inv, b0.y), 0.f);
                r0.z = fmaxf(fmaf(acc[2], inv, b0.z), 0.f);
                r0.w = fmaxf(fmaf(acc[3], inv, b0.w), 0.f);
                r1.x = fmaxf(fmaf(acc[4], inv, b1.x), 0.f);
                r1.y = fmaxf(fmaf(acc[5], inv, b1.y), 0.f);
                r1.z = fmaxf(fmaf(acc[6], inv, b1.z), 0.f);
                r1.w = fmaxf(fmaf(acc[7], inv, b1.w), 0.f);
                float4* hrow = reinterpret_cast<float4*>(&hs[nl][0]);
                hrow[c * 2]     = r0;
                hrow[c * 2 + 1] = r1;
            }
        }
    }
    __syncthreads();

    // Phase B: projection. tx = output column, w in registers, 8 nodes/thread.
    const int tx = threadIdx.x, ty = threadIdx.y;
    float w[64];
    if (DO == 64 || tx < DO) {
#pragma unroll
        for (int k = 0; k < 64; k++) w[k] = Ws[tx * 65 + k];  // conflict-free
    } else {
#pragma unroll
        for (int k = 0; k < 64; k++) w[k] = 0.f;
    }
#pragma unroll
    for (int j = 0; j < 8; j++) {
        int nl = ty * 8 + j;
        int gn = nbase + nl;
        const float4* hrow = reinterpret_cast<const float4*>(&hs[nl][0]);
        float a = 0.f;
#pragma unroll
        for (int k4 = 0; k4 < 16; k4++) {
            float4 hv = hrow[k4];  // warp-uniform broadcast
            a = fmaf(hv.x, w[4 * k4 + 0], a);
            a = fmaf(hv.y, w[4 * k4 + 1], a);
            a = fmaf(hv.z, w[4 * k4 + 2], a);
            a = fmaf(hv.w, w[4 * k4 + 3], a);
        }
        if (gn < NN) pout[gn * 64 + tx] = __float2half_rn(a);
    }
}

// ------------------------------------------------------------- final layer --
// out = (gather p2 + self)*inv + b2, 40 cols (chunks 5..7 of p2 are zeros).
__global__ __launch_bounds__(256) void fin_k(const float* __restrict__ bv,
                                             const __half* __restrict__ pin,
                                             float* __restrict__ out) {
    const int tid = threadIdx.x;
    const int warp = tid >> 5, lane = tid & 31;
    const int es = lane >> 3, c = lane & 7;
    const int node = blockIdx.x * 8 + warp;

    const int s0 = __ldg(&g_off[node]);
    const int s1 = __ldg(&g_off[node + 1]);

    float acc[8];
    gather_node(pin, node, s0, s1, es, c, acc);

    if (es == 0 && c < 5) {
        float inv = 1.f / (float)(s1 - s0 + 1);
        const float4* bv4 = reinterpret_cast<const float4*>(bv);
        float4 b0 = __ldg(&bv4[c * 2]);
        float4 b1 = __ldg(&bv4[c * 2 + 1]);
        float4 r0, r1;
        r0.x = fmaf(acc[0], inv, b0.x);
        r0.y = fmaf(acc[1], inv, b0.y);
        r0.z = fmaf(acc[2], inv, b0.z);
        r0.w = fmaf(acc[3], inv, b0.w);
        r1.x = fmaf(acc[4], inv, b1.x);
        r1.y = fmaf(acc[5], inv, b1.y);
        r1.z = fmaf(acc[6], inv, b1.z);
        r1.w = fmaf(acc[7], inv, b1.w);
        float4* out4 = reinterpret_cast<float4*>(out);
        out4[node * 10 + c * 2]     = r0;
        out4[node * 10 + c * 2 + 1] = r1;
    }
}

// ----------------------------------------------------------------- launch ---
extern "C" void kernel_launch(void* const* d_in, const int* in_sizes, int n_in,
                              void* d_out, int out_size) {
    const float* feats = (const float*)d_in[0];
    const int*   src   = (const int*)d_in[1];
    const int*   dst   = (const int*)d_in[2];
    const float* W0 = (const float*)d_in[3];
    const float* b0 = (const float*)d_in[4];
    const float* W1 = (const float*)d_in[5];
    const float* b1 = (const float*)d_in[6];
    const float* W2 = (const float*)d_in[7];
    const float* b2 = (const float*)d_in[8];
    float* out = (float*)d_out;

    void *pA_v = nullptr, *pB_v = nullptr;
    cudaGetSymbolAddress(&pA_v, g_pA);
    cudaGetSymbolAddress(&pB_v, g_pB);
    __half* pA = (__half*)pA_v;
    __half* pB = (__half*)pB_v;

    // CSR build
    deg_zero_k<<<(NN + 255) / 256, 256>>>();
    deg_count_k<<<(NE / 4 + 255) / 256, 256>>>((const int4*)dst);
    scan_bsum_k<<<NB, 1024>>>();
    scan_write_k<<<NB, 1024>>>();
    fill_k<<<(NE / 4 + 255) / 256, 256>>>((const int4*)src, (const int4*)dst);

    const int GB_L = (NN + 63) / 64;  // 1563
    const dim3 LB(64, 8);

    // k0: p0 = feats @ W0^T
    gemm_k<<<GB_L, LB>>>(feats, W0, pA);
    // k1: h1 = relu(agg(p0)*inv + b0); p1 = h1 @ W1^T
    layer_k<64><<<GB_L, LB>>>(b0, W1, pA, pB);
    // k2: h2 = relu(agg(p1)*inv + b1); p2 = h2 @ W2^T (40-wide, zero-padded)
    layer_k<40><<<GB_L, LB>>>(b1, W2, pB, pA);
    // k3: out = agg(p2)*inv + b2
    fin_k<<<NN / 8, 256>>>(b2, pA, out);
}

// round 15
// speedup vs baseline: 1.3297x; 1.2202x over previous
#include <cuda_runtime.h>
#include <cuda_fp16.h>

// GraphSAGE 3-layer GCN aggregator. N=100000, E=1600000, 64->64->64->40.
//
// Restructure: ((segsum(h[src]) + h) * inv) @ W^T + b
//            = (segsum(p[src])  + p) * inv + b   with p = h @ W^T
// p stored fp16 (one 128B line per node row); accum/weights fp32.
// layer_k (R11 skeleton, 512 thr, 16 nodes/block):
//   Phase A: warp per node, collective gather (4 edge-slots x 8 col-chunks).
//   Phase B: thread owns output col o for TWO nodes (gg, gg+8), sharing each
//            W float4 load between both accumulators (halves W crossbar
//            traffic vs loading the row once per output).

constexpr int NN = 100000;
constexpr int NE = 1600000;
constexpr int NB = (NN + 1023) / 1024;  // 98 scan blocks

__device__ __half g_pA[NN * 64];
__device__ __half g_pB[NN * 64];
__device__ int    g_deg[NN];
__device__ int    g_off[NN + 1];
__device__ int    g_cur[NN];
__device__ int    g_esrc[NE];
__device__ int    g_bsum[NB];

// ---------------------------------------------------------------- degrees ---
__global__ void deg_zero_k() {
    int i = blockIdx.x * 256 + threadIdx.x;
    if (i < NN) g_deg[i] = 0;
}

__global__ void deg_count_k(const int4* __restrict__ dst4) {
    int i = blockIdx.x * 256 + threadIdx.x;
    if (i < NE / 4) {
        int4 d = __ldg(&dst4[i]);
        atomicAdd(&g_deg[d.x], 1);
        atomicAdd(&g_deg[d.y], 1);
        atomicAdd(&g_deg[d.z], 1);
        atomicAdd(&g_deg[d.w], 1);
    }
}

// ------------------------------------------------------------------- scan ---
__global__ __launch_bounds__(1024) void scan_bsum_k() {
    int i = blockIdx.x * 1024 + threadIdx.x;
    int v = (i < NN) ? g_deg[i] : 0;
#pragma unroll
    for (int o = 16; o; o >>= 1) v += __shfl_down_sync(~0u, v, o);
    __shared__ int ws[32];
    if ((threadIdx.x & 31) == 0) ws[threadIdx.x >> 5] = v;
    __syncthreads();
    if (threadIdx.x < 32) {
        int s = ws[threadIdx.x];
#pragma unroll
        for (int o = 16; o; o >>= 1) s += __shfl_down_sync(~0u, s, o);
        if (threadIdx.x == 0) g_bsum[blockIdx.x] = s;
    }
}

// scan_write with inlined cross-block partials (each block sums g_bsum[<bid]).
__global__ __launch_bounds__(1024) void scan_write_k() {
    const int lane = threadIdx.x & 31, w = threadIdx.x >> 5;

    int part = (threadIdx.x < blockIdx.x) ? g_bsum[threadIdx.x] : 0;
#pragma unroll
    for (int o = 16; o; o >>= 1) part += __shfl_down_sync(~0u, part, o);
    __shared__ int ws2[32];
    if (lane == 0) ws2[w] = part;
    __syncthreads();
    __shared__ int boff_s;
    if (threadIdx.x < 32) {
        int s = ws2[threadIdx.x];
#pragma unroll
        for (int o = 16; o; o >>= 1) s += __shfl_down_sync(~0u, s, o);
        if (threadIdx.x == 0) boff_s = s;
    }

    int i = blockIdx.x * 1024 + threadIdx.x;
    int v = (i < NN) ? g_deg[i] : 0;
    int x = v;
#pragma unroll
    for (int o = 1; o < 32; o <<= 1) {
        int y = __shfl_up_sync(~0u, x, o);
        if (lane >= o) x += y;
    }
    __shared__ int ws[32], sws[32];
    if (lane == 31) ws[w] = x;
    __syncthreads();
    if (threadIdx.x < 32) {
        int s = ws[threadIdx.x];
        int xx = s;
#pragma unroll
        for (int o = 1; o < 32; o <<= 1) {
            int y = __shfl_up_sync(~0u, xx, o);
            if (lane >= o) xx += y;
        }
        sws[threadIdx.x] = xx - s;  // exclusive warp prefix
    }
    __syncthreads();
    int incl = x + sws[w] + boff_s;
    int excl = incl - v;
    if (i < NN) {
        g_off[i] = excl;
        g_cur[i] = excl;
        if (i == NN - 1) g_off[NN] = incl;
    }
}

// ------------------------------------------------------------------- fill ---
__global__ void fill_k(const int4* __restrict__ src4,
                       const int4* __restrict__ dst4) {
    int i = blockIdx.x * 256 + threadIdx.x;
    if (i < NE / 4) {
        int4 s = __ldg(&src4[i]);
        int4 d = __ldg(&dst4[i]);
        g_esrc[atomicAdd(&g_cur[d.x], 1)] = s.x;
        g_esrc[atomicAdd(&g_cur[d.y], 1)] = s.y;
        g_esrc[atomicAdd(&g_cur[d.z], 1)] = s.z;
        g_esrc[atomicAdd(&g_cur[d.w], 1)] = s.w;
    }
}

// --------------------------------------------------------------- gather -----
__device__ __forceinline__ void add8(float acc[8], uint4 u) {
    __half2* h = reinterpret_cast<__half2*>(&u);
#pragma unroll
    for (int j = 0; j < 4; j++) {
        float2 f = __half22float2(h[j]);
        acc[2 * j]     += f.x;
        acc[2 * j + 1] += f.y;
    }
}

// Warp-collective gather of one node's aggregated row (self + neighbors).
// es = lane>>3 (edge slot 0..3), c = lane&7 (16B column chunk).
__device__ __forceinline__ void gather_node(const __half* __restrict__ pin,
                                            int node, int s0, int s1,
                                            int es, int c, float acc[8]) {
#pragma unroll
    for (int j = 0; j < 8; j++) acc[j] = 0.f;
    if (es == 0)
        add8(acc, __ldg(reinterpret_cast<const uint4*>(pin + node * 64) + c));

    int e = s0;
    for (; e + 8 <= s1; e += 8) {
        int i0 = __ldg(&g_esrc[e + es]);
        int i1 = __ldg(&g_esrc[e + 4 + es]);
        uint4 u0 = __ldg(reinterpret_cast<const uint4*>(pin + i0 * 64) + c);
        uint4 u1 = __ldg(reinterpret_cast<const uint4*>(pin + i1 * 64) + c);
        add8(acc, u0);
        add8(acc, u1);
    }
    for (; e < s1; e += 4) {
        int ee = e + es;
        if (ee < s1) {
            int i0 = __ldg(&g_esrc[ee]);
            add8(acc, __ldg(reinterpret_cast<const uint4*>(pin + i0 * 64) + c));
        }
    }
#pragma unroll
    for (int j = 0; j < 8; j++) {
        acc[j] += __shfl_xor_sync(~0u, acc[j], 8);
        acc[j] += __shfl_xor_sync(~0u, acc[j], 16);
    }
}

// ------------------------------------------------------------------- gemm ---
// k0: p0 = feats @ W0^T (fp32 in, fp16 out). Block (64,8)=512thr, 64 nodes.
__global__ __launch_bounds__(512) void gemm_k(const float* __restrict__ h,
                                              const float* __restrict__ W,
                                              __half* __restrict__ p) {
    __shared__ float Ws[64 * 65];
    __shared__ __align__(16) float hs[8][64];
    const int tx = threadIdx.x, ty = threadIdx.y;
    const int tid = ty * 64 + tx;
    for (int i = tid; i < 64 * 64; i += 512)
        Ws[(i >> 6) * 65 + (i & 63)] = W[i];
    __syncthreads();
    float w[64];
#pragma unroll
    for (int k = 0; k < 64; k++) w[k] = Ws[tx * 65 + k];

    const int base = blockIdx.x * 64;
#pragma unroll
    for (int it = 0; it < 8; it++) {
        int n = base + it * 8 + ty;
        __syncthreads();
        if (n < NN) hs[ty][tx] = h[n * 64 + tx];
        __syncthreads();
        if (n < NN) {
            const float4* hrow = reinterpret_cast<const float4*>(&hs[ty][0]);
            float acc = 0.f;
#pragma unroll
            for (int k4 = 0; k4 < 16; k4++) {
                float4 hv = hrow[k4];
                acc = fmaf(hv.x, w[4 * k4 + 0], acc);
                acc = fmaf(hv.y, w[4 * k4 + 1], acc);
                acc = fmaf(hv.z, w[4 * k4 + 2], acc);
                acc = fmaf(hv.w, w[4 * k4 + 3], acc);
            }
            p[n * 64 + tx] = __float2half_rn(acc);
        }
    }
}

// ---------------------------------------------------------- fused layer -----
// 512 threads = 16 warps = 16 nodes/block (grid 6250 exact).
// Phase A: each warp gathers one node; epilogue relu(agg*inv + b) -> hs.
// Phase B: thread owns output column o = tid&63 for node pair
// (gpair, gpair+8); each W float4 load feeds both accumulators.
// pout fp16, stride 64, zero-filled for o >= DO.
template <int DO>
__global__ __launch_bounds__(512) void layer_k(const float* __restrict__ bv,
                                               const float* __restrict__ W,
                                               const __half* __restrict__ pin,
                                               __half* __restrict__ pout) {
    __shared__ __align__(16) float Ws[64 * 68];
    __shared__ __align__(16) float hs[16][68];
    const int tid = threadIdx.x;
    const int warp = tid >> 5, lane = tid & 31;
    const int es = lane >> 3, c = lane & 7;
    const int node = blockIdx.x * 16 + warp;

    for (int i = tid; i < DO * 64; i += 512)
        Ws[(i >> 6) * 68 + (i & 63)] = W[i];

    const int s0 = __ldg(&g_off[node]);
    const int s1 = __ldg(&g_off[node + 1]);

    float acc[8];
    gather_node(pin, node, s0, s1, es, c, acc);

    if (es == 0) {
        float inv = 1.f / (float)(s1 - s0 + 1);
        const float4* bv4 = reinterpret_cast<const float4*>(bv);
        float4 b0 = __ldg(&bv4[c * 2]);
        float4 b1 = __ldg(&bv4[c * 2 + 1]);
        float4 r0, r1;
        r0.x = fmaxf(fmaf(acc[0], inv, b0.x), 0.f);
        r0.y = fmaxf(fmaf(acc[1], inv, b0.y), 0.f);
        r0.z = fmaxf(fmaf(acc[2], inv, b0.z), 0.f);
        r0.w = fmaxf(fmaf(acc[3], inv, b0.w), 0.f);
        r1.x = fmaxf(fmaf(acc[4], inv, b1.x), 0.f);
        r1.y = fmaxf(fmaf(acc[5], inv, b1.y), 0.f);
        r1.z = fmaxf(fmaf(acc[6], inv, b1.z), 0.f);
        r1.w = fmaxf(fmaf(acc[7], inv, b1.w), 0.f);
        float4* hrow = reinterpret_cast<float4*>(&hs[warp][0]);
        hrow[c * 2]     = r0;
        hrow[c * 2 + 1] = r1;
    }
    __syncthreads();

    // Phase B: o = tid&63; two nodes per thread share every W load.
    const int o = tid & 63;
    const int gpair = tid >> 6;  // 0..7
    float a0 = 0.f, a1 = 0.f;
    if (DO == 64 || o < DO) {
        const float4* w4 = reinterpret_cast<const float4*>(&Ws[o * 68]);
        const float4* h0 = reinterpret_cast<const float4*>(&hs[gpair][0]);
        const float4* h1 = reinterpret_cast<const float4*>(&hs[gpair + 8][0]);
#pragma unroll
        for (int k4 = 0; k4 < 16; k4++) {
            float4 wv = w4[k4];       // shared between both outputs
            float4 x0 = h0[k4];       // warp-uniform broadcast
            float4 x1 = h1[k4];       // warp-uniform broadcast
            a0 = fmaf(x0.x, wv.x, a0);
            a1 = fmaf(x1.x, wv.x, a1);
            a0 = fmaf(x0.y, wv.y, a0);
            a1 = fmaf(x1.y, wv.y, a1);
            a0 = fmaf(x0.z, wv.z, a0);
            a1 = fmaf(x1.z, wv.z, a1);
            a0 = fmaf(x0.w, wv.w, a0);
            a1 = fmaf(x1.w, wv.w, a1);
        }
    }
    const int nb = blockIdx.x * 16;
    pout[(nb + gpair) * 64 + o]     = __float2half_rn(a0);
    pout[(nb + gpair + 8) * 64 + o] = __float2half_rn(a1);
}

// ------------------------------------------------------------- final layer --
// out = (gather p2 + self)*inv + b2, 40 cols (chunks 5..7 of p2 are zeros).
__global__ __launch_bounds__(256) void fin_k(const float* __restrict__ bv,
                                             const __half* __restrict__ pin,
                                             float* __restrict__ out) {
    const int tid = threadIdx.x;
    const int warp = tid >> 5, lane = tid & 31;
    const int es = lane >> 3, c = lane & 7;
    const int node = blockIdx.x * 8 + warp;

    const int s0 = __ldg(&g_off[node]);
    const int s1 = __ldg(&g_off[node + 1]);

    float acc[8];
    gather_node(pin, node, s0, s1, es, c, acc);

    if (es == 0 && c < 5) {
        float inv = 1.f / (float)(s1 - s0 + 1);
        const float4* bv4 = reinterpret_cast<const float4*>(bv);
        float4 b0 = __ldg(&bv4[c * 2]);
        float4 b1 = __ldg(&bv4[c * 2 + 1]);
        float4 r0, r1;
        r0.x = fmaf(acc[0], inv, b0.x);
        r0.y = fmaf(acc[1], inv, b0.y);
        r0.z = fmaf(acc[2], inv, b0.z);
        r0.w = fmaf(acc[3], inv, b0.w);
        r1.x = fmaf(acc[4], inv, b1.x);
        r1.y = fmaf(acc[5], inv, b1.y);
        r1.z = fmaf(acc[6], inv, b1.z);
        r1.w = fmaf(acc[7], inv, b1.w);
        float4* out4 = reinterpret_cast<float4*>(out);
        out4[node * 10 + c * 2]     = r0;
        out4[node * 10 + c * 2 + 1] = r1;
    }
}

// ----------------------------------------------------------------- launch ---
extern "C" void kernel_launch(void* const* d_in, const int* in_sizes, int n_in,
                              void* d_out, int out_size) {
    const float* feats = (const float*)d_in[0];
    const int*   src   = (const int*)d_in[1];
    const int*   dst   = (const int*)d_in[2];
    const float* W0 = (const float*)d_in[3];
    const float* b0 = (const float*)d_in[4];
    const float* W1 = (const float*)d_in[5];
    const float* b1 = (const float*)d_in[6];
    const float* W2 = (const float*)d_in[7];
    const float* b2 = (const float*)d_in[8];
    float* out = (float*)d_out;

    void *pA_v = nullptr, *pB_v = nullptr;
    cudaGetSymbolAddress(&pA_v, g_pA);
    cudaGetSymbolAddress(&pB_v, g_pB);
    __half* pA = (__half*)pA_v;
    __half* pB = (__half*)pB_v;

    // CSR build
    deg_zero_k<<<(NN + 255) / 256, 256>>>();
    deg_count_k<<<(NE / 4 + 255) / 256, 256>>>((const int4*)dst);
    scan_bsum_k<<<NB, 1024>>>();
    scan_write_k<<<NB, 1024>>>();
    fill_k<<<(NE / 4 + 255) / 256, 256>>>((const int4*)src, (const int4*)dst);

    // k0: p0 = feats @ W0^T
    gemm_k<<<(NN + 63) / 64, dim3(64, 8)>>>(feats, W0, pA);
    // k1: h1 = relu(agg(p0)*inv + b0); p1 = h1 @ W1^T
    layer_k<64><<<NN / 16, 512>>>(b0, W1, pA, pB);
    // k2: h2 = relu(agg(p1)*inv + b1); p2 = h2 @ W2^T (40-wide, zero-padded)
    layer_k<40><<<NN / 16, 512>>>(b1, W2, pB, pA);
    // k3: out = agg(p2)*inv + b2
    fin_k<<<NN / 8, 256>>>(b2, pA, out);
}

// round 16
// speedup vs baseline: 1.4770x; 1.1108x over previous
#include <cuda_runtime.h>
#include <cuda_fp16.h>

// GraphSAGE 3-layer GCN aggregator. N=100000, E=1600000, 64->64->64->40.
//
// Restructure: ((segsum(h[src]) + h) * inv) @ W^T + b
//            = (segsum(p[src])  + p) * inv + b   with p = h @ W^T
// p stored fp16 (one 128B line per node row); accum/weights fp32.
// layer_k: 512 thr, 32 nodes/block.
//   Phase A: warp-collective gather (4 edge-slots x 8 col-chunks), 2 nodes
//            per warp; epilogue relu(agg*inv+b) -> hs.
//   Phase B: thread owns output col o for FOUR nodes (gpair+{0,8,16,24});
//            each W float4 LDS feeds 4 accumulators (crossbar amortized 4x);
//            h reads are warp-uniform broadcasts.

constexpr int NN = 100000;
constexpr int NE = 1600000;
constexpr int NB = (NN + 1023) / 1024;  // 98 scan blocks

__device__ __half g_pA[NN * 64];
__device__ __half g_pB[NN * 64];
__device__ int    g_deg[NN];
__device__ int    g_off[NN + 1];
__device__ int    g_cur[NN];
__device__ int    g_esrc[NE];
__device__ int    g_bsum[NB];

// ---------------------------------------------------------------- degrees ---
__global__ void deg_zero_k() {
    int i = blockIdx.x * 256 + threadIdx.x;
    if (i < NN) g_deg[i] = 0;
}

__global__ void deg_count_k(const int4* __restrict__ dst4) {
    int i = blockIdx.x * 256 + threadIdx.x;
    if (i < NE / 4) {
        int4 d = __ldg(&dst4[i]);
        atomicAdd(&g_deg[d.x], 1);
        atomicAdd(&g_deg[d.y], 1);
        atomicAdd(&g_deg[d.z], 1);
        atomicAdd(&g_deg[d.w], 1);
    }
}

// ------------------------------------------------------------------- scan ---
__global__ __launch_bounds__(1024) void scan_bsum_k() {
    int i = blockIdx.x * 1024 + threadIdx.x;
    int v = (i < NN) ? g_deg[i] : 0;
#pragma unroll
    for (int o = 16; o; o >>= 1) v += __shfl_down_sync(~0u, v, o);
    __shared__ int ws[32];
    if ((threadIdx.x & 31) == 0) ws[threadIdx.x >> 5] = v;
    __syncthreads();
    if (threadIdx.x < 32) {
        int s = ws[threadIdx.x];
#pragma unroll
        for (int o = 16; o; o >>= 1) s += __shfl_down_sync(~0u, s, o);
        if (threadIdx.x == 0) g_bsum[blockIdx.x] = s;
    }
}

// scan_write with inlined cross-block partials (each block sums g_bsum[<bid]).
__global__ __launch_bounds__(1024) void scan_write_k() {
    const int lane = threadIdx.x & 31, w = threadIdx.x >> 5;

    int part = (threadIdx.x < blockIdx.x) ? g_bsum[threadIdx.x] : 0;
#pragma unroll
    for (int o = 16; o; o >>= 1) part += __shfl_down_sync(~0u, part, o);
    __shared__ int ws2[32];
    if (lane == 0) ws2[w] = part;
    __syncthreads();
    __shared__ int boff_s;
    if (threadIdx.x < 32) {
        int s = ws2[threadIdx.x];
#pragma unroll
        for (int o = 16; o; o >>= 1) s += __shfl_down_sync(~0u, s, o);
        if (threadIdx.x == 0) boff_s = s;
    }

    int i = blockIdx.x * 1024 + threadIdx.x;
    int v = (i < NN) ? g_deg[i] : 0;
    int x = v;
#pragma unroll
    for (int o = 1; o < 32; o <<= 1) {
        int y = __shfl_up_sync(~0u, x, o);
        if (lane >= o) x += y;
    }
    __shared__ int ws[32], sws[32];
    if (lane == 31) ws[w] = x;
    __syncthreads();
    if (threadIdx.x < 32) {
        int s = ws[threadIdx.x];
        int xx = s;
#pragma unroll
        for (int o = 1; o < 32; o <<= 1) {
            int y = __shfl_up_sync(~0u, xx, o);
            if (lane >= o) xx += y;
        }
        sws[threadIdx.x] = xx - s;  // exclusive warp prefix
    }
    __syncthreads();
    int incl = x + sws[w] + boff_s;
    int excl = incl - v;
    if (i < NN) {
        g_off[i] = excl;
        g_cur[i] = excl;
        if (i == NN - 1) g_off[NN] = incl;
    }
}

// ------------------------------------------------------------------- fill ---
__global__ void fill_k(const int4* __restrict__ src4,
                       const int4* __restrict__ dst4) {
    int i = blockIdx.x * 256 + threadIdx.x;
    if (i < NE / 4) {
        int4 s = __ldg(&src4[i]);
        int4 d = __ldg(&dst4[i]);
        g_esrc[atomicAdd(&g_cur[d.x], 1)] = s.x;
        g_esrc[atomicAdd(&g_cur[d.y], 1)] = s.y;
        g_esrc[atomicAdd(&g_cur[d.z], 1)] = s.z;
        g_esrc[atomicAdd(&g_cur[d.w], 1)] = s.w;
    }
}

// --------------------------------------------------------------- gather -----
__device__ __forceinline__ void add8(float acc[8], uint4 u) {
    __half2* h = reinterpret_cast<__half2*>(&u);
#pragma unroll
    for (int j = 0; j < 4; j++) {
        float2 f = __half22float2(h[j]);
        acc[2 * j]     += f.x;
        acc[2 * j + 1] += f.y;
    }
}

// Warp-collective gather of one node's aggregated row (self + neighbors).
// es = lane>>3 (edge slot 0..3), c = lane&7 (16B column chunk).
__device__ __forceinline__ void gather_node(const __half* __restrict__ pin,
                                            int node, int s0, int s1,
                                            int es, int c, float acc[8]) {
#pragma unroll
    for (int j = 0; j < 8; j++) acc[j] = 0.f;
    if (es == 0)
        add8(acc, __ldg(reinterpret_cast<const uint4*>(pin + node * 64) + c));

    int e = s0;
    for (; e + 8 <= s1; e += 8) {
        int i0 = __ldg(&g_esrc[e + es]);
        int i1 = __ldg(&g_esrc[e + 4 + es]);
        uint4 u0 = __ldg(reinterpret_cast<const uint4*>(pin + i0 * 64) + c);
        uint4 u1 = __ldg(reinterpret_cast<const uint4*>(pin + i1 * 64) + c);
        add8(acc, u0);
        add8(acc, u1);
    }
    for (; e < s1; e += 4) {
        int ee = e + es;
        if (ee < s1) {
            int i0 = __ldg(&g_esrc[ee]);
            add8(acc, __ldg(reinterpret_cast<const uint4*>(pin + i0 * 64) + c));
        }
    }
#pragma unroll
    for (int j = 0; j < 8; j++) {
        acc[j] += __shfl_xor_sync(~0u, acc[j], 8);
        acc[j] += __shfl_xor_sync(~0u, acc[j], 16);
    }
}

// Gather epilogue: relu((agg)*inv + b) -> hs row (es==0 lanes write).
__device__ __forceinline__ void epilogue_relu(const float acc[8], int es, int c,
                                              float inv,
                                              const float* __restrict__ bv,
                                              float* __restrict__ hrow_f) {
    if (es == 0) {
        const float4* bv4 = reinterpret_cast<const float4*>(bv);
        float4 b0 = __ldg(&bv4[c * 2]);
        float4 b1 = __ldg(&bv4[c * 2 + 1]);
        float4 r0, r1;
        r0.x = fmaxf(fmaf(acc[0], inv, b0.x), 0.f);
        r0.y = fmaxf(fmaf(acc[1], inv, b0.y), 0.f);
        r0.z = fmaxf(fmaf(acc[2], inv, b0.z), 0.f);
        r0.w = fmaxf(fmaf(acc[3], inv, b0.w), 0.f);
        r1.x = fmaxf(fmaf(acc[4], inv, b1.x), 0.f);
        r1.y = fmaxf(fmaf(acc[5], inv, b1.y), 0.f);
        r1.z = fmaxf(fmaf(acc[6], inv, b1.z), 0.f);
        r1.w = fmaxf(fmaf(acc[7], inv, b1.w), 0.f);
        float4* hrow = reinterpret_cast<float4*>(hrow_f);
        hrow[c * 2]     = r0;
        hrow[c * 2 + 1] = r1;
    }
}

// ------------------------------------------------------------------- gemm ---
// k0: p0 = feats @ W0^T (fp32 in, fp16 out). Block (64,8)=512thr, 64 nodes.
__global__ __launch_bounds__(512) void gemm_k(const float* __restrict__ h,
                                              const float* __restrict__ W,
                                              __half* __restrict__ p) {
    __shared__ float Ws[64 * 65];
    __shared__ __align__(16) float hs[8][64];
    const int tx = threadIdx.x, ty = threadIdx.y;
    const int tid = ty * 64 + tx;
    for (int i = tid; i < 64 * 64; i += 512)
        Ws[(i >> 6) * 65 + (i & 63)] = W[i];
    __syncthreads();
    float w[64];
#pragma unroll
    for (int k = 0; k < 64; k++) w[k] = Ws[tx * 65 + k];

    const int base = blockIdx.x * 64;
#pragma unroll
    for (int it = 0; it < 8; it++) {
        int n = base + it * 8 + ty;
        __syncthreads();
        if (n < NN) hs[ty][tx] = h[n * 64 + tx];
        __syncthreads();
        if (n < NN) {
            const float4* hrow = reinterpret_cast<const float4*>(&hs[ty][0]);
            float acc = 0.f;
#pragma unroll
            for (int k4 = 0; k4 < 16; k4++) {
                float4 hv = hrow[k4];
                acc = fmaf(hv.x, w[4 * k4 + 0], acc);
                acc = fmaf(hv.y, w[4 * k4 + 1], acc);
                acc = fmaf(hv.z, w[4 * k4 + 2], acc);
                acc = fmaf(hv.w, w[4 * k4 + 3], acc);
            }
            p[n * 64 + tx] = __float2half_rn(acc);
        }
    }
}

// ---------------------------------------------------------- fused layer -----
// 512 threads = 16 warps, 32 nodes per block (grid 3125 exact).
// Phase A: warp gathers nodes (warp, warp+16); epilogue -> hs rows.
// Phase B: thread owns col o = tid&63 for nodes gpair+{0,8,16,24}; every W
// float4 LDS feeds 4 accumulators. pout fp16 stride 64, zeros for o >= DO.
template <int DO>
__global__ __launch_bounds__(512) void layer_k(const float* __restrict__ bv,
                                               const float* __restrict__ W,
                                               const __half* __restrict__ pin,
                                               __half* __restrict__ pout) {
    __shared__ __align__(16) float Ws[64 * 68];
    __shared__ __align__(16) float hs[32][68];
    const int tid = threadIdx.x;
    const int warp = tid >> 5, lane = tid & 31;
    const int es = lane >> 3, c = lane & 7;
    const int nbase = blockIdx.x * 32;

    for (int i = tid; i < DO * 64; i += 512)
        Ws[(i >> 6) * 68 + (i & 63)] = W[i];

    // Phase A: two nodes per warp
#pragma unroll 1
    for (int half = 0; half < 2; half++) {
        const int nl = warp + half * 16;
        const int node = nbase + nl;
        const int s0 = __ldg(&g_off[node]);
        const int s1 = __ldg(&g_off[node + 1]);
        float acc[8];
        gather_node(pin, node, s0, s1, es, c, acc);
        float inv = 1.f / (float)(s1 - s0 + 1);
        epilogue_relu(acc, es, c, inv, bv, &hs[nl][0]);
    }
    __syncthreads();

    // Phase B: 4 nodes per thread share every W load.
    const int o = tid & 63;
    const int gpair = tid >> 6;  // 0..7
    float a0 = 0.f, a1 = 0.f, a2 = 0.f, a3 = 0.f;
    if (DO == 64 || o < DO) {
        const float4* w4 = reinterpret_cast<const float4*>(&Ws[o * 68]);
        const float4* h0 = reinterpret_cast<const float4*>(&hs[gpair][0]);
        const float4* h1 = reinterpret_cast<const float4*>(&hs[gpair + 8][0]);
        const float4* h2 = reinterpret_cast<const float4*>(&hs[gpair + 16][0]);
        const float4* h3 = reinterpret_cast<const float4*>(&hs[gpair + 24][0]);
#pragma unroll
        for (int k4 = 0; k4 < 16; k4++) {
            float4 wv = w4[k4];   // shared by 4 outputs
            float4 x0 = h0[k4];   // warp-uniform broadcasts
            float4 x1 = h1[k4];
            float4 x2 = h2[k4];
            float4 x3 = h3[k4];
            a0 = fmaf(x0.x, wv.x, a0);
            a1 = fmaf(x1.x, wv.x, a1);
            a2 = fmaf(x2.x, wv.x, a2);
            a3 = fmaf(x3.x, wv.x, a3);
            a0 = fmaf(x0.y, wv.y, a0);
            a1 = fmaf(x1.y, wv.y, a1);
            a2 = fmaf(x2.y, wv.y, a2);
            a3 = fmaf(x3.y, wv.y, a3);
            a0 = fmaf(x0.z, wv.z, a0);
            a1 = fmaf(x1.z, wv.z, a1);
            a2 = fmaf(x2.z, wv.z, a2);
            a3 = fmaf(x3.z, wv.z, a3);
            a0 = fmaf(x0.w, wv.w, a0);
            a1 = fmaf(x1.w, wv.w, a1);
            a2 = fmaf(x2.w, wv.w, a2);
            a3 = fmaf(x3.w, wv.w, a3);
        }
    }
    pout[(nbase + gpair) * 64 + o]      = __float2half_rn(a0);
    pout[(nbase + gpair + 8) * 64 + o]  = __float2half_rn(a1);
    pout[(nbase + gpair + 16) * 64 + o] = __float2half_rn(a2);
    pout[(nbase + gpair + 24) * 64 + o] = __float2half_rn(a3);
}

// ------------------------------------------------------------- final layer --
// out = (gather p2 + self)*inv + b2, 40 cols (chunks 5..7 of p2 are zeros).
__global__ __launch_bounds__(256) void fin_k(const float* __restrict__ bv,
                                             const __half* __restrict__ pin,
                                             float* __restrict__ out) {
    const int tid = threadIdx.x;
    const int warp = tid >> 5, lane = tid & 31;
    const int es = lane >> 3, c = lane & 7;
    const int node = blockIdx.x * 8 + warp;

    const int s0 = __ldg(&g_off[node]);
    const int s1 = __ldg(&g_off[node + 1]);

    float acc[8];
    gather_node(pin, node, s0, s1, es, c, acc);

    if (es == 0 && c < 5) {
        float inv = 1.f / (float)(s1 - s0 + 1);
        const float4* bv4 = reinterpret_cast<const float4*>(bv);
        float4 b0 = __ldg(&bv4[c * 2]);
        float4 b1 = __ldg(&bv4[c * 2 + 1]);
        float4 r0, r1;
        r0.x = fmaf(acc[0], inv, b0.x);
        r0.y = fmaf(acc[1], inv, b0.y);
        r0.z = fmaf(acc[2], inv, b0.z);
        r0.w = fmaf(acc[3], inv, b0.w);
        r1.x = fmaf(acc[4], inv, b1.x);
        r1.y = fmaf(acc[5], inv, b1.y);
        r1.z = fmaf(acc[6], inv, b1.z);
        r1.w = fmaf(acc[7], inv, b1.w);
        float4* out4 = reinterpret_cast<float4*>(out);
        out4[node * 10 + c * 2]     = r0;
        out4[node * 10 + c * 2 + 1] = r1;
    }
}

// ----------------------------------------------------------------- launch ---
extern "C" void kernel_launch(void* const* d_in, const int* in_sizes, int n_in,
                              void* d_out, int out_size) {
    const float* feats = (const float*)d_in[0];
    const int*   src   = (const int*)d_in[1];
    const int*   dst   = (const int*)d_in[2];
    const float* W0 = (const float*)d_in[3];
    const float* b0 = (const float*)d_in[4];
    const float* W1 = (const float*)d_in[5];
    const float* b1 = (const float*)d_in[6];
    const float* W2 = (const float*)d_in[7];
    const float* b2 = (const float*)d_in[8];
    float* out = (float*)d_out;

    void *pA_v = nullptr, *pB_v = nullptr;
    cudaGetSymbolAddress(&pA_v, g_pA);
    cudaGetSymbolAddress(&pB_v, g_pB);
    __half* pA = (__half*)pA_v;
    __half* pB = (__half*)pB_v;

    // CSR build
    deg_zero_k<<<(NN + 255) / 256, 256>>>();
    deg_count_k<<<(NE / 4 + 255) / 256, 256>>>((const int4*)dst);
    scan_bsum_k<<<NB, 1024>>>();
    scan_write_k<<<NB, 1024>>>();
    fill_k<<<(NE / 4 + 255) / 256, 256>>>((const int4*)src, (const int4*)dst);

    // k0: p0 = feats @ W0^T
    gemm_k<<<(NN + 63) / 64, dim3(64, 8)>>>(feats, W0, pA);
    // k1: h1 = relu(agg(p0)*inv + b0); p1 = h1 @ W1^T
    layer_k<64><<<NN / 32, 512>>>(b0, W1, pA, pB);
    // k2: h2 = relu(agg(p1)*inv + b1); p2 = h2 @ W2^T (40-wide, zero-padded)
    layer_k<40><<<NN / 32, 512>>>(b1, W2, pB, pA);
    // k3: out = agg(p2)*inv + b2
    fin_k<<<NN / 8, 256>>>(b2, pA, out);
}